// round 3
// baseline (speedup 1.0000x reference)
#include <cuda_runtime.h>

#define BB   4
#define CIN  64
#define COUT 64
#define NPTS 8192
#define KNN  16
#define NQ   (BB * NPTS)
#define CAP  192
#define SAMP 1024
#define TCB  1024   // candidates per collect tile (512 pairs)

// Static scratch (no runtime allocation allowed)
__device__ int   g_idx[NQ * KNN];   // [q][k]      2 MB
__device__ float g_z[NQ * COUT];    // zT[b][n][o] 8 MB
__device__ float g_thr[NQ];         // per-query threshold
__device__ int   g_flag[NQ];        // needs exact fallback

// --------------------------- f32x2 helpers ---------------------------------
__device__ __forceinline__ unsigned long long pk2(float lo, float hi) {
    unsigned long long r;
    asm("mov.b64 %0, {%1, %2};" : "=l"(r) : "f"(lo), "f"(hi));
    return r;
}
__device__ __forceinline__ void upk2(unsigned long long v, float& lo, float& hi) {
    asm("mov.b64 {%0, %1}, %2;" : "=f"(lo), "=f"(hi) : "l"(v));
}
__device__ __forceinline__ unsigned long long mul2(unsigned long long a, unsigned long long b) {
    unsigned long long r;
    asm("mul.rn.f32x2 %0, %1, %2;" : "=l"(r) : "l"(a), "l"(b));
    return r;
}
__device__ __forceinline__ unsigned long long add2(unsigned long long a, unsigned long long b) {
    unsigned long long r;
    asm("add.rn.f32x2 %0, %1, %2;" : "=l"(r) : "l"(a), "l"(b));
    return r;
}
__device__ __forceinline__ unsigned long long fma2(unsigned long long a, unsigned long long b,
                                                   unsigned long long c) {
    unsigned long long r;
    asm("fma.rn.f32x2 %0, %1, %2, %3;" : "=l"(r) : "l"(a), "l"(b), "l"(c));
    return r;
}

// ---------------------------------------------------------------------------
// Kernel A: per-query threshold = 8th smallest distance over a shared
// 1024-candidate subsample (stride 8). Index-free min/max bubble.
// ---------------------------------------------------------------------------
__global__ void __launch_bounds__(128) knn_thresh(const float* __restrict__ coords) {
    __shared__ float4 sp[SAMP];
    int tid = threadIdx.x;
    int b   = blockIdx.x >> 6;                  // 64 blocks per batch
    const float* cb = coords + b * 3 * NPTS;

    for (int t = tid; t < SAMP; t += 128) {
        int j = t * 8;
        float cx = cb[j], cy = cb[NPTS + j], cz = cb[2 * NPTS + j];
        sp[t] = make_float4(cx, cy, cz, (cx * cx + cy * cy) + cz * cz);
    }
    __syncthreads();

    int q = blockIdx.x * 128 + tid;
    int n = q & (NPTS - 1);
    float qx = cb[n], qy = cb[NPTS + n], qz = cb[2 * NPTS + n];
    float sqi = (qx * qx + qy * qy) + qz * qz;

    float ds[8];
#pragma unroll
    for (int s = 0; s < 8; s++) ds[s] = __int_as_float(0x7f800000);

#pragma unroll 4
    for (int t = 0; t < SAMP; t++) {
        float4 c = sp[t];
        float inner = fmaf(qz, c.z, fmaf(qy, c.y, qx * c.x));
        float d = fmaf(-2.0f, inner, sqi + c.w);
        if (d < ds[7]) {
            float v = d;
#pragma unroll
            for (int s = 0; s < 8; s++) {
                float lo = fminf(ds[s], v);
                float hi = fmaxf(ds[s], v);
                ds[s] = lo; v = hi;
            }
        }
    }
    g_thr[q] = ds[7];
}

// ---------------------------------------------------------------------------
// Kernel B: full scan with packed f32x2 distance math; collect (d, j) with
// d <= T into a PER-THREAD LOCAL buffer (~64 hits expected), then select the
// exact top-16 from the buffer. Flags rare queries needing exact fallback.
// ---------------------------------------------------------------------------
__global__ void __launch_bounds__(128) knn_collect(const float* __restrict__ coords) {
    __shared__ float4 sxy[TCB / 2];   // (x0,x1,y0,y1) per pair
    __shared__ float4 szw[TCB / 2];   // (z0,z1,sq0,sq1) per pair

    unsigned long long buf[CAP];      // local memory (per-thread stack)

    int tid = threadIdx.x;
    int q   = blockIdx.x * 128 + tid;
    int b   = blockIdx.x >> 6;
    int n   = q & (NPTS - 1);
    const float* cb = coords + b * 3 * NPTS;

    float qx = cb[n], qy = cb[NPTS + n], qz = cb[2 * NPTS + n];
    float sqi = (qx * qx + qy * qy) + qz * qz;

    unsigned long long qx2 = pk2(qx, qx), qy2 = pk2(qy, qy), qz2 = pk2(qz, qz);
    unsigned long long sq2 = pk2(sqi, sqi);
    unsigned long long m2  = pk2(-2.0f, -2.0f);

    float T = g_thr[q];
    int cnt = 0;

    for (int tb = 0; tb < NPTS; tb += TCB) {
        __syncthreads();
        float* fxy = (float*)sxy;
        float* fzw = (float*)szw;
        for (int e = tid; e < TCB; e += 128) {
            int j = tb + e;
            float cx = cb[j], cy = cb[NPTS + j], cz = cb[2 * NPTS + j];
            int p = e >> 1, o = e & 1;
            fxy[p * 4 + o]     = cx;
            fxy[p * 4 + 2 + o] = cy;
            fzw[p * 4 + o]     = cz;
            fzw[p * 4 + 2 + o] = (cx * cx + cy * cy) + cz * cz;
        }
        __syncthreads();

#pragma unroll 8
        for (int p = 0; p < TCB / 2; p++) {
            float4 a  = sxy[p];
            float4 zz = szw[p];
            unsigned long long x01 = pk2(a.x, a.y),  y01 = pk2(a.z, a.w);
            unsigned long long z01 = pk2(zz.x, zz.y), w01 = pk2(zz.z, zz.w);
            unsigned long long t0 = mul2(qx2, x01);
            t0 = fma2(qy2, y01, t0);
            t0 = fma2(qz2, z01, t0);
            unsigned long long d2 = fma2(m2, t0, add2(sq2, w01));
            float d0, d1;
            upk2(d2, d0, d1);
            if (fminf(d0, d1) <= T) {
                int j0 = tb + 2 * p;
                if (d0 <= T && cnt < CAP) {
                    buf[cnt] = ((unsigned long long)(unsigned)j0 << 32) | __float_as_uint(d0);
                    cnt++;
                }
                if (d1 <= T && cnt < CAP) {
                    buf[cnt] = ((unsigned long long)(unsigned)(j0 + 1) << 32) | __float_as_uint(d1);
                    cnt++;
                }
            }
        }
    }

    // Exact top-16 from buffered candidates (ascending-j order + strict-less
    // insertion reproduces top_k's lowest-index tie-break).
    float ds[KNN];
    int   is_[KNN];
#pragma unroll
    for (int s = 0; s < KNN; s++) { ds[s] = __int_as_float(0x7f800000); is_[s] = 0; }

    for (int t = 0; t < cnt; t++) {
        unsigned long long e = buf[t];
        float d = __uint_as_float((unsigned)e);
        int   j = (int)(e >> 32);
        if (d < ds[KNN - 1]) {
            float vd = d; int vi = j;
#pragma unroll
            for (int s = 0; s < KNN; s++) {
                float od = ds[s]; int oi = is_[s];
                bool  pr = vd < od;
                ds[s]  = pr ? vd : od;
                is_[s] = pr ? vi : oi;
                vd     = pr ? od : vd;
                vi     = pr ? oi : vi;
            }
        }
    }

    int* op = g_idx + q * KNN;
#pragma unroll
    for (int s = 0; s < KNN; s++) op[s] = is_[s];
    // cnt saturates at CAP: cnt==CAP may mean overflow -> fall back too.
    g_flag[q] = (cnt < KNN || cnt >= CAP) ? 1 : 0;
}

// ---------------------------------------------------------------------------
// Kernel C: exact fallback for flagged queries (expected ~0-5 of 32768).
// ---------------------------------------------------------------------------
__global__ void __launch_bounds__(256) knn_fallback(const float* __restrict__ coords) {
    int q = blockIdx.x * 256 + threadIdx.x;
    if (!g_flag[q]) return;
    int b = q >> 13, n = q & (NPTS - 1);
    const float* cb = coords + b * 3 * NPTS;
    float qx = cb[n], qy = cb[NPTS + n], qz = cb[2 * NPTS + n];
    float sqi = (qx * qx + qy * qy) + qz * qz;

    float ds[KNN];
    int   is_[KNN];
#pragma unroll
    for (int s = 0; s < KNN; s++) { ds[s] = __int_as_float(0x7f800000); is_[s] = 0; }

    for (int j = 0; j < NPTS; j++) {
        float cx = __ldg(cb + j), cy = __ldg(cb + NPTS + j), cz = __ldg(cb + 2 * NPTS + j);
        float sq = (cx * cx + cy * cy) + cz * cz;
        float inner = fmaf(qz, cz, fmaf(qy, cy, qx * cx));
        float d = fmaf(-2.0f, inner, sqi + sq);
        if (d < ds[KNN - 1]) {
            float vd = d; int vi = j;
#pragma unroll
            for (int s = 0; s < KNN; s++) {
                float od = ds[s]; int oi = is_[s];
                bool  pr = vd < od;
                ds[s]  = pr ? vd : od;
                is_[s] = pr ? vi : oi;
                vd     = pr ? od : vd;
                vi     = pr ? oi : vi;
            }
        }
    }
    int* op = g_idx + q * KNN;
#pragma unroll
    for (int s = 0; s < KNN; s++) op[s] = is_[s];
}

// ---------------------------------------------------------------------------
// Kernel: z[b][n][o] = sum_c W[o][c] * x[b][c][n]   (stored n-major)
// 512 blocks of 128 threads (64 n-cols x 2 o-halves) for occupancy.
// ---------------------------------------------------------------------------
__global__ void __launch_bounds__(128) gemm_kernel(const float* __restrict__ x,
                                                   const float* __restrict__ W) {
    __shared__ float ws[COUT * CIN];
    int tid = threadIdx.x;
#pragma unroll
    for (int u = 0; u < 8; u++)
        ((float4*)ws)[tid + u * 128] = ((const float4*)W)[tid + u * 128];
    __syncthreads();

    int b     = blockIdx.x >> 7;          // 128 n-tiles of 64 per batch
    int ntile = (blockIdx.x & 127) * 64;
    int nl    = tid & 63;
    int o0    = (tid >> 6) * 32;
    int n     = ntile + nl;

    const float* xb = x + b * CIN * NPTS;

    float acc[32];
#pragma unroll
    for (int i = 0; i < 32; i++) acc[i] = 0.0f;

    for (int c = 0; c < CIN; c += 4) {
        float xv0 = xb[(c + 0) * NPTS + n];
        float xv1 = xb[(c + 1) * NPTS + n];
        float xv2 = xb[(c + 2) * NPTS + n];
        float xv3 = xb[(c + 3) * NPTS + n];
#pragma unroll
        for (int i = 0; i < 32; i++) {
            float4 w4 = *(const float4*)&ws[(o0 + i) * CIN + c];
            acc[i] = fmaf(w4.x, xv0, acc[i]);
            acc[i] = fmaf(w4.y, xv1, acc[i]);
            acc[i] = fmaf(w4.z, xv2, acc[i]);
            acc[i] = fmaf(w4.w, xv3, acc[i]);
        }
    }

    float* zp = g_z + ((size_t)b * NPTS + n) * COUT + o0;
#pragma unroll
    for (int i = 0; i < 32; i += 4)
        *(float4*)&zp[i] = make_float4(acc[i], acc[i + 1], acc[i + 2], acc[i + 3]);
}

// ---------------------------------------------------------------------------
// Kernel: y[b][o][n] = max_k z[b][idx[b][n][k]][o]
// ---------------------------------------------------------------------------
__global__ void __launch_bounds__(256) maxgather_kernel(float* __restrict__ y) {
    __shared__ float yt[COUT][33];

    int tid = threadIdx.x;
    int w   = tid >> 5;
    int l   = tid & 31;
    int b     = blockIdx.x >> 8;
    int ntile = (blockIdx.x & 255) * 32;

    const float* zb = g_z + (size_t)b * NPTS * COUT;
    const float NEG_INF = __int_as_float(0xff800000);

    for (int qq = 0; qq < 4; qq++) {
        int nl = w * 4 + qq;
        int n  = ntile + nl;
        const int* ip = g_idx + ((size_t)b * NPTS + n) * KNN;
        float m0 = NEG_INF, m1 = NEG_INF;
#pragma unroll
        for (int k = 0; k < KNN; k++) {
            int r = __ldg(&ip[k]);
            const float* zr = zb + (size_t)r * COUT;
            m0 = fmaxf(m0, zr[l]);
            m1 = fmaxf(m1, zr[l + 32]);
        }
        yt[l][nl]      = m0;
        yt[l + 32][nl] = m1;
    }
    __syncthreads();

#pragma unroll
    for (int e = tid; e < COUT * 32; e += 256) {
        int o  = e >> 5;
        int nl = e & 31;
        y[((size_t)b * COUT + o) * NPTS + ntile + nl] = yt[o][nl];
    }
}

// ---------------------------------------------------------------------------
extern "C" void kernel_launch(void* const* d_in, const int* in_sizes, int n_in,
                              void* d_out, int out_size) {
    const float* x      = (const float*)d_in[0];
    const float* coords = (const float*)d_in[1];
    const float* W      = (const float*)d_in[2];
    float*       out    = (float*)d_out;

    gemm_kernel<<<BB * 128, 128>>>(x, W);
    knn_thresh<<<NQ / 128, 128>>>(coords);
    knn_collect<<<NQ / 128, 128>>>(coords);
    knn_fallback<<<NQ / 256, 256>>>(coords);
    maxgather_kernel<<<BB * (NPTS / 32), 256>>>(out);

    cudaMemcpyAsync(out + (size_t)BB * COUT * NPTS, coords,
                    (size_t)BB * 3 * NPTS * sizeof(float),
                    cudaMemcpyDeviceToDevice, 0);
}

// round 4
// speedup vs baseline: 2.7713x; 2.7713x over previous
#include <cuda_runtime.h>

#define BB   4
#define CIN  64
#define COUT 64
#define NPTS 8192
#define KNN  16
#define NQ   (BB * NPTS)
#define CAP  192
#define SAMP 1024
#define TCB  1024   // candidates per collect tile (512 pairs)

// Static scratch (no runtime allocation allowed)
__device__ int   g_idx[NQ * KNN];   // [q][k]      2 MB
__device__ float g_z[NQ * COUT];    // zT[b][n][o] 8 MB
__device__ float g_thr[NQ];         // per-query threshold
__device__ int   g_flag[NQ];        // needs exact fallback

// --------------------------- f32x2 helpers ---------------------------------
__device__ __forceinline__ unsigned long long pk2(float lo, float hi) {
    unsigned long long r;
    asm("mov.b64 %0, {%1, %2};" : "=l"(r) : "f"(lo), "f"(hi));
    return r;
}
__device__ __forceinline__ void upk2(unsigned long long v, float& lo, float& hi) {
    asm("mov.b64 {%0, %1}, %2;" : "=f"(lo), "=f"(hi) : "l"(v));
}
__device__ __forceinline__ unsigned long long mul2(unsigned long long a, unsigned long long b) {
    unsigned long long r;
    asm("mul.rn.f32x2 %0, %1, %2;" : "=l"(r) : "l"(a), "l"(b));
    return r;
}
__device__ __forceinline__ unsigned long long add2(unsigned long long a, unsigned long long b) {
    unsigned long long r;
    asm("add.rn.f32x2 %0, %1, %2;" : "=l"(r) : "l"(a), "l"(b));
    return r;
}
__device__ __forceinline__ unsigned long long fma2(unsigned long long a, unsigned long long b,
                                                   unsigned long long c) {
    unsigned long long r;
    asm("fma.rn.f32x2 %0, %1, %2, %3;" : "=l"(r) : "l"(a), "l"(b), "l"(c));
    return r;
}

// ---------------------------------------------------------------------------
// Kernel A: per-query threshold = 8th smallest distance over a shared
// 1024-candidate subsample (stride 8). Index-free min/max bubble.
// ---------------------------------------------------------------------------
__global__ void __launch_bounds__(128) knn_thresh(const float* __restrict__ coords) {
    __shared__ float4 sp[SAMP];
    int tid = threadIdx.x;
    int b   = blockIdx.x >> 6;                  // 64 blocks per batch
    const float* cb = coords + b * 3 * NPTS;

    for (int t = tid; t < SAMP; t += 128) {
        int j = t * 8;
        float cx = cb[j], cy = cb[NPTS + j], cz = cb[2 * NPTS + j];
        sp[t] = make_float4(cx, cy, cz, (cx * cx + cy * cy) + cz * cz);
    }
    __syncthreads();

    int q = blockIdx.x * 128 + tid;
    int n = q & (NPTS - 1);
    float qx = cb[n], qy = cb[NPTS + n], qz = cb[2 * NPTS + n];
    float sqi = (qx * qx + qy * qy) + qz * qz;

    float ds[8];
#pragma unroll
    for (int s = 0; s < 8; s++) ds[s] = __int_as_float(0x7f800000);

#pragma unroll 4
    for (int t = 0; t < SAMP; t++) {
        float4 c = sp[t];
        float inner = fmaf(qz, c.z, fmaf(qy, c.y, qx * c.x));
        float d = fmaf(-2.0f, inner, sqi + c.w);
        if (d < ds[7]) {
            float v = d;
#pragma unroll
            for (int s = 0; s < 8; s++) {
                float lo = fminf(ds[s], v);
                float hi = fmaxf(ds[s], v);
                ds[s] = lo; v = hi;
            }
        }
    }
    g_thr[q] = ds[7];
}

// ---------------------------------------------------------------------------
// Kernel B: full scan with packed f32x2 distance math; collect (d, j) with
// d <= T into a per-thread local buffer (~64 hits expected), then select the
// exact top-16 from the buffer. Flags rare queries needing exact fallback.
// ---------------------------------------------------------------------------
__global__ void __launch_bounds__(128) knn_collect(const float* __restrict__ coords) {
    __shared__ float4 sxy[TCB / 2];   // (x0,x1,y0,y1) per pair
    __shared__ float4 szw[TCB / 2];   // (z0,z1,sq0,sq1) per pair

    unsigned long long buf[CAP];      // local memory (per-thread stack)

    int tid = threadIdx.x;
    int q   = blockIdx.x * 128 + tid;
    int b   = blockIdx.x >> 6;
    int n   = q & (NPTS - 1);
    const float* cb = coords + b * 3 * NPTS;

    float qx = cb[n], qy = cb[NPTS + n], qz = cb[2 * NPTS + n];
    float sqi = (qx * qx + qy * qy) + qz * qz;

    unsigned long long qx2 = pk2(qx, qx), qy2 = pk2(qy, qy), qz2 = pk2(qz, qz);
    unsigned long long sq2 = pk2(sqi, sqi);
    unsigned long long m2  = pk2(-2.0f, -2.0f);

    float T = g_thr[q];
    int cnt = 0;

    for (int tb = 0; tb < NPTS; tb += TCB) {
        __syncthreads();
        float* fxy = (float*)sxy;
        float* fzw = (float*)szw;
        for (int e = tid; e < TCB; e += 128) {
            int j = tb + e;
            float cx = cb[j], cy = cb[NPTS + j], cz = cb[2 * NPTS + j];
            int p = e >> 1, o = e & 1;
            fxy[p * 4 + o]     = cx;
            fxy[p * 4 + 2 + o] = cy;
            fzw[p * 4 + o]     = cz;
            fzw[p * 4 + 2 + o] = (cx * cx + cy * cy) + cz * cz;
        }
        __syncthreads();

#pragma unroll 8
        for (int p = 0; p < TCB / 2; p++) {
            float4 a  = sxy[p];
            float4 zz = szw[p];
            unsigned long long x01 = pk2(a.x, a.y),  y01 = pk2(a.z, a.w);
            unsigned long long z01 = pk2(zz.x, zz.y), w01 = pk2(zz.z, zz.w);
            unsigned long long t0 = mul2(qx2, x01);
            t0 = fma2(qy2, y01, t0);
            t0 = fma2(qz2, z01, t0);
            unsigned long long d2 = fma2(m2, t0, add2(sq2, w01));
            float d0, d1;
            upk2(d2, d0, d1);
            if (fminf(d0, d1) <= T) {
                int j0 = tb + 2 * p;
                if (d0 <= T && cnt < CAP) {
                    buf[cnt] = ((unsigned long long)(unsigned)j0 << 32) | __float_as_uint(d0);
                    cnt++;
                }
                if (d1 <= T && cnt < CAP) {
                    buf[cnt] = ((unsigned long long)(unsigned)(j0 + 1) << 32) | __float_as_uint(d1);
                    cnt++;
                }
            }
        }
    }

    // Exact top-16 from buffered candidates (ascending-j order + strict-less
    // insertion reproduces top_k's lowest-index tie-break).
    float ds[KNN];
    int   is_[KNN];
#pragma unroll
    for (int s = 0; s < KNN; s++) { ds[s] = __int_as_float(0x7f800000); is_[s] = 0; }

    for (int t = 0; t < cnt; t++) {
        unsigned long long e = buf[t];
        float d = __uint_as_float((unsigned)e);
        int   j = (int)(e >> 32);
        if (d < ds[KNN - 1]) {
            float vd = d; int vi = j;
#pragma unroll
            for (int s = 0; s < KNN; s++) {
                float od = ds[s]; int oi = is_[s];
                bool  pr = vd < od;
                ds[s]  = pr ? vd : od;
                is_[s] = pr ? vi : oi;
                vd     = pr ? od : vd;
                vi     = pr ? oi : vi;
            }
        }
    }

    int* op = g_idx + q * KNN;
#pragma unroll
    for (int s = 0; s < KNN; s++) op[s] = is_[s];
    // cnt saturates at CAP: cnt==CAP may mean overflow -> fall back too.
    g_flag[q] = (cnt < KNN || cnt >= CAP) ? 1 : 0;
}

// ---------------------------------------------------------------------------
// Kernel C: warp-cooperative exact fallback. One 32-thread block per query;
// non-flagged blocks exit immediately. Each lane scans 256 interleaved
// candidates keeping a sorted top-16, then a 16-step warp merge selects the
// global top-16 by lexicographic (d, j) — exact top_k tie-break.
// ---------------------------------------------------------------------------
__global__ void __launch_bounds__(32) knn_fallback(const float* __restrict__ coords) {
    int q = blockIdx.x;
    if (!g_flag[q]) return;

    int lane = threadIdx.x;
    int b = q >> 13, n = q & (NPTS - 1);
    const float* cb = coords + b * 3 * NPTS;
    float qx = cb[n], qy = cb[NPTS + n], qz = cb[2 * NPTS + n];
    float sqi = (qx * qx + qy * qy) + qz * qz;

    float ds[KNN];
    int   is_[KNN];
#pragma unroll
    for (int s = 0; s < KNN; s++) { ds[s] = __int_as_float(0x7f800000); is_[s] = 0x7fffffff; }

    // Lane-interleaved scan: ascending j within each lane.
    for (int i = 0; i < NPTS / 32; i++) {
        int j = i * 32 + lane;
        float cx = cb[j], cy = cb[NPTS + j], cz = cb[2 * NPTS + j];
        float sq = (cx * cx + cy * cy) + cz * cz;
        float inner = fmaf(qz, cz, fmaf(qy, cy, qx * cx));
        float d = fmaf(-2.0f, inner, sqi + sq);
        if (d < ds[KNN - 1]) {
            float vd = d; int vi = j;
#pragma unroll
            for (int s = 0; s < KNN; s++) {
                float od = ds[s]; int oi = is_[s];
                bool  pr = vd < od;
                ds[s]  = pr ? vd : od;
                is_[s] = pr ? vi : oi;
                vd     = pr ? od : vd;
                vi     = pr ? oi : vi;
            }
        }
    }

    // Spill sorted per-lane lists to smem for dynamic-index access.
    __shared__ float sd[32][KNN];
    __shared__ int   sj[32][KNN];
#pragma unroll
    for (int s = 0; s < KNN; s++) { sd[lane][s] = ds[s]; sj[lane][s] = is_[s]; }
    __syncwarp();

    // 16-round warp merge: lexicographic-min (d, j) across lane heads.
    int ptr = 0;
    for (int k = 0; k < KNN; k++) {
        float cd = (ptr < KNN) ? sd[lane][ptr] : __int_as_float(0x7f800000);
        int   cj = (ptr < KNN) ? sj[lane][ptr] : 0x7fffffff;
        float wd = cd; int wj = cj;
#pragma unroll
        for (int off = 16; off > 0; off >>= 1) {
            float od = __shfl_xor_sync(0xffffffffu, wd, off);
            int   oj = __shfl_xor_sync(0xffffffffu, wj, off);
            if (od < wd || (od == wd && oj < wj)) { wd = od; wj = oj; }
        }
        if (wd == cd && wj == cj) ptr++;   // unique j -> exactly one lane advances
        if (lane == 0) g_idx[q * KNN + k] = wj;
    }
}

// ---------------------------------------------------------------------------
// Kernel: z[b][n][o] = sum_c W[o][c] * x[b][c][n]   (stored n-major)
// 512 blocks of 128 threads (64 n-cols x 2 o-halves) for occupancy.
// ---------------------------------------------------------------------------
__global__ void __launch_bounds__(128) gemm_kernel(const float* __restrict__ x,
                                                   const float* __restrict__ W) {
    __shared__ float ws[COUT * CIN];
    int tid = threadIdx.x;
#pragma unroll
    for (int u = 0; u < 8; u++)
        ((float4*)ws)[tid + u * 128] = ((const float4*)W)[tid + u * 128];
    __syncthreads();

    int b     = blockIdx.x >> 7;          // 128 n-tiles of 64 per batch
    int ntile = (blockIdx.x & 127) * 64;
    int nl    = tid & 63;
    int o0    = (tid >> 6) * 32;
    int n     = ntile + nl;

    const float* xb = x + b * CIN * NPTS;

    float acc[32];
#pragma unroll
    for (int i = 0; i < 32; i++) acc[i] = 0.0f;

    for (int c = 0; c < CIN; c += 4) {
        float xv0 = xb[(c + 0) * NPTS + n];
        float xv1 = xb[(c + 1) * NPTS + n];
        float xv2 = xb[(c + 2) * NPTS + n];
        float xv3 = xb[(c + 3) * NPTS + n];
#pragma unroll
        for (int i = 0; i < 32; i++) {
            float4 w4 = *(const float4*)&ws[(o0 + i) * CIN + c];
            acc[i] = fmaf(w4.x, xv0, acc[i]);
            acc[i] = fmaf(w4.y, xv1, acc[i]);
            acc[i] = fmaf(w4.z, xv2, acc[i]);
            acc[i] = fmaf(w4.w, xv3, acc[i]);
        }
    }

    float* zp = g_z + ((size_t)b * NPTS + n) * COUT + o0;
#pragma unroll
    for (int i = 0; i < 32; i += 4)
        *(float4*)&zp[i] = make_float4(acc[i], acc[i + 1], acc[i + 2], acc[i + 3]);
}

// ---------------------------------------------------------------------------
// Kernel: y[b][o][n] = max_k z[b][idx[b][n][k]][o]
// ---------------------------------------------------------------------------
__global__ void __launch_bounds__(256) maxgather_kernel(float* __restrict__ y) {
    __shared__ float yt[COUT][33];

    int tid = threadIdx.x;
    int w   = tid >> 5;
    int l   = tid & 31;
    int b     = blockIdx.x >> 8;
    int ntile = (blockIdx.x & 255) * 32;

    const float* zb = g_z + (size_t)b * NPTS * COUT;
    const float NEG_INF = __int_as_float(0xff800000);

    for (int qq = 0; qq < 4; qq++) {
        int nl = w * 4 + qq;
        int n  = ntile + nl;
        const int* ip = g_idx + ((size_t)b * NPTS + n) * KNN;
        float m0 = NEG_INF, m1 = NEG_INF;
#pragma unroll
        for (int k = 0; k < KNN; k++) {
            int r = __ldg(&ip[k]);
            const float* zr = zb + (size_t)r * COUT;
            m0 = fmaxf(m0, zr[l]);
            m1 = fmaxf(m1, zr[l + 32]);
        }
        yt[l][nl]      = m0;
        yt[l + 32][nl] = m1;
    }
    __syncthreads();

#pragma unroll
    for (int e = tid; e < COUT * 32; e += 256) {
        int o  = e >> 5;
        int nl = e & 31;
        y[((size_t)b * COUT + o) * NPTS + ntile + nl] = yt[o][nl];
    }
}

// ---------------------------------------------------------------------------
extern "C" void kernel_launch(void* const* d_in, const int* in_sizes, int n_in,
                              void* d_out, int out_size) {
    const float* x      = (const float*)d_in[0];
    const float* coords = (const float*)d_in[1];
    const float* W      = (const float*)d_in[2];
    float*       out    = (float*)d_out;

    gemm_kernel<<<BB * 128, 128>>>(x, W);
    knn_thresh<<<NQ / 128, 128>>>(coords);
    knn_collect<<<NQ / 128, 128>>>(coords);
    knn_fallback<<<NQ, 32>>>(coords);
    maxgather_kernel<<<BB * (NPTS / 32), 256>>>(out);

    cudaMemcpyAsync(out + (size_t)BB * COUT * NPTS, coords,
                    (size_t)BB * 3 * NPTS * sizeof(float),
                    cudaMemcpyDeviceToDevice, 0);
}

// round 5
// speedup vs baseline: 2.8815x; 1.0398x over previous
#include <cuda_runtime.h>

#define BB   4
#define CIN  64
#define COUT 64
#define NPTS 8192
#define KNN  16
#define NQ   (BB * NPTS)
#define CAP  192
#define SAMP 1024
#define TCB  1024   // candidates per collect tile (512 pairs)

// Static scratch (no runtime allocation allowed)
__device__ int   g_idx[NQ * KNN];   // [q][k]      2 MB
__device__ float g_z[NQ * COUT];    // zT[b][n][o] 8 MB
__device__ int   g_wcount;          // fallback worklist size
__device__ int   g_wlist[NQ];       // fallback worklist

// --------------------------- f32x2 helpers ---------------------------------
__device__ __forceinline__ unsigned long long pk2(float lo, float hi) {
    unsigned long long r;
    asm("mov.b64 %0, {%1, %2};" : "=l"(r) : "f"(lo), "f"(hi));
    return r;
}
__device__ __forceinline__ void upk2(unsigned long long v, float& lo, float& hi) {
    asm("mov.b64 {%0, %1}, %2;" : "=f"(lo), "=f"(hi) : "l"(v));
}
__device__ __forceinline__ unsigned long long mul2(unsigned long long a, unsigned long long b) {
    unsigned long long r;
    asm("mul.rn.f32x2 %0, %1, %2;" : "=l"(r) : "l"(a), "l"(b));
    return r;
}
__device__ __forceinline__ unsigned long long add2(unsigned long long a, unsigned long long b) {
    unsigned long long r;
    asm("add.rn.f32x2 %0, %1, %2;" : "=l"(r) : "l"(a), "l"(b));
    return r;
}
__device__ __forceinline__ unsigned long long fma2(unsigned long long a, unsigned long long b,
                                                   unsigned long long c) {
    unsigned long long r;
    asm("fma.rn.f32x2 %0, %1, %2, %3;" : "=l"(r) : "l"(a), "l"(b), "l"(c));
    return r;
}

// ---------------------------------------------------------------------------
// Kernel B (fused): per-thread threshold (8th smallest over stride-8 sample),
// then full scan with packed f32x2 math, collecting hits d<=T into a local
// buffer; exact top-16 from the buffer. Flags rare queries to the worklist.
// ---------------------------------------------------------------------------
__global__ void __launch_bounds__(128) knn_collect(const float* __restrict__ coords) {
    __shared__ float4 stile[TCB];     // phase 1: sample [SAMP]; phase 2: 2 planes of TCB/2

    unsigned long long buf[CAP];      // per-thread local (stack)

    int tid = threadIdx.x;
    int q   = blockIdx.x * 128 + tid;
    int b   = blockIdx.x >> 6;        // 64 blocks per batch
    int n   = q & (NPTS - 1);
    const float* cb = coords + b * 3 * NPTS;

    float qx = cb[n], qy = cb[NPTS + n], qz = cb[2 * NPTS + n];
    float sqi = (qx * qx + qy * qy) + qz * qz;

    // ---- Phase 1: threshold from stride-8 subsample -----------------------
    for (int t = tid; t < SAMP; t += 128) {
        int j = t * 8;
        float cx = cb[j], cy = cb[NPTS + j], cz = cb[2 * NPTS + j];
        stile[t] = make_float4(cx, cy, cz, (cx * cx + cy * cy) + cz * cz);
    }
    __syncthreads();

    float t8[8];
#pragma unroll
    for (int s = 0; s < 8; s++) t8[s] = __int_as_float(0x7f800000);
#pragma unroll 4
    for (int t = 0; t < SAMP; t++) {
        float4 c = stile[t];
        float inner = fmaf(qz, c.z, fmaf(qy, c.y, qx * c.x));
        float d = fmaf(-2.0f, inner, sqi + c.w);
        if (d < t8[7]) {
            float v = d;
#pragma unroll
            for (int s = 0; s < 8; s++) {
                float lo = fminf(t8[s], v);
                float hi = fmaxf(t8[s], v);
                t8[s] = lo; v = hi;
            }
        }
    }
    float T = t8[7];

    // ---- Phase 2: full scan + collect -------------------------------------
    unsigned long long qx2 = pk2(qx, qx), qy2 = pk2(qy, qy), qz2 = pk2(qz, qz);
    unsigned long long sq2 = pk2(sqi, sqi);
    unsigned long long m2  = pk2(-2.0f, -2.0f);

    float4* sxy = stile;              // (x0,x1,y0,y1) per pair  [TCB/2]
    float4* szw = stile + TCB / 2;    // (z0,z1,sq0,sq1) per pair [TCB/2]
    int cnt = 0;

    for (int tb = 0; tb < NPTS; tb += TCB) {
        __syncthreads();
        float* fxy = (float*)sxy;
        float* fzw = (float*)szw;
        for (int e = tid; e < TCB; e += 128) {
            int j = tb + e;
            float cx = cb[j], cy = cb[NPTS + j], cz = cb[2 * NPTS + j];
            int p = e >> 1, o = e & 1;
            fxy[p * 4 + o]     = cx;
            fxy[p * 4 + 2 + o] = cy;
            fzw[p * 4 + o]     = cz;
            fzw[p * 4 + 2 + o] = (cx * cx + cy * cy) + cz * cz;
        }
        __syncthreads();

#pragma unroll 8
        for (int p = 0; p < TCB / 2; p++) {
            float4 a  = sxy[p];
            float4 zz = szw[p];
            unsigned long long x01 = pk2(a.x, a.y),  y01 = pk2(a.z, a.w);
            unsigned long long z01 = pk2(zz.x, zz.y), w01 = pk2(zz.z, zz.w);
            unsigned long long t0 = mul2(qx2, x01);
            t0 = fma2(qy2, y01, t0);
            t0 = fma2(qz2, z01, t0);
            unsigned long long d2 = fma2(m2, t0, add2(sq2, w01));
            float d0, d1;
            upk2(d2, d0, d1);
            if (fminf(d0, d1) <= T) {
                int j0 = tb + 2 * p;
                if (d0 <= T && cnt < CAP) {
                    buf[cnt] = ((unsigned long long)(unsigned)j0 << 32) | __float_as_uint(d0);
                    cnt++;
                }
                if (d1 <= T && cnt < CAP) {
                    buf[cnt] = ((unsigned long long)(unsigned)(j0 + 1) << 32) | __float_as_uint(d1);
                    cnt++;
                }
            }
        }
    }

    // Exact top-16 from buffered candidates (ascending-j order + strict-less
    // insertion reproduces top_k's lowest-index tie-break).
    float ds[KNN];
    int   is_[KNN];
#pragma unroll
    for (int s = 0; s < KNN; s++) { ds[s] = __int_as_float(0x7f800000); is_[s] = 0; }

    for (int t = 0; t < cnt; t++) {
        unsigned long long e = buf[t];
        float d = __uint_as_float((unsigned)e);
        int   j = (int)(e >> 32);
        if (d < ds[KNN - 1]) {
            float vd = d; int vi = j;
#pragma unroll
            for (int s = 0; s < KNN; s++) {
                float od = ds[s]; int oi = is_[s];
                bool  pr = vd < od;
                ds[s]  = pr ? vd : od;
                is_[s] = pr ? vi : oi;
                vd     = pr ? od : vd;
                vi     = pr ? oi : vi;
            }
        }
    }

    int* op = g_idx + q * KNN;
#pragma unroll
    for (int s = 0; s < KNN; s++) op[s] = is_[s];

    // cnt saturates at CAP: cnt==CAP may mean overflow -> fall back too.
    if (cnt < KNN || cnt >= CAP) {
        int slot = atomicAdd(&g_wcount, 1);
        g_wlist[slot] = q;
    }
}

// ---------------------------------------------------------------------------
// Kernel C: worklist-driven exact fallback. Fixed 256 blocks x 1 warp;
// blocks grid-stride over the (tiny) worklist. Warp-cooperative scan:
// per-lane sorted top-16 over 256 interleaved candidates, then a 16-round
// lexicographic (d, j) warp merge — exact top_k tie-break.
// ---------------------------------------------------------------------------
__global__ void __launch_bounds__(32) knn_fallback(const float* __restrict__ coords) {
    int lane = threadIdx.x;
    int nw = g_wcount;

    for (int w = blockIdx.x; w < nw; w += 256) {
        int q = g_wlist[w];
        int b = q >> 13, n = q & (NPTS - 1);
        const float* cb = coords + b * 3 * NPTS;
        float qx = cb[n], qy = cb[NPTS + n], qz = cb[2 * NPTS + n];
        float sqi = (qx * qx + qy * qy) + qz * qz;

        float ds[KNN];
        int   is_[KNN];
#pragma unroll
        for (int s = 0; s < KNN; s++) { ds[s] = __int_as_float(0x7f800000); is_[s] = 0x7fffffff; }

        for (int i = 0; i < NPTS / 32; i++) {
            int j = i * 32 + lane;
            float cx = cb[j], cy = cb[NPTS + j], cz = cb[2 * NPTS + j];
            float sq = (cx * cx + cy * cy) + cz * cz;
            float inner = fmaf(qz, cz, fmaf(qy, cy, qx * cx));
            float d = fmaf(-2.0f, inner, sqi + sq);
            if (d < ds[KNN - 1]) {
                float vd = d; int vi = j;
#pragma unroll
                for (int s = 0; s < KNN; s++) {
                    float od = ds[s]; int oi = is_[s];
                    bool  pr = vd < od;
                    ds[s]  = pr ? vd : od;
                    is_[s] = pr ? vi : oi;
                    vd     = pr ? od : vd;
                    vi     = pr ? oi : vi;
                }
            }
        }

        __shared__ float sd[32][KNN];
        __shared__ int   sj[32][KNN];
#pragma unroll
        for (int s = 0; s < KNN; s++) { sd[lane][s] = ds[s]; sj[lane][s] = is_[s]; }
        __syncwarp();

        int ptr = 0;
        for (int k = 0; k < KNN; k++) {
            float cd = (ptr < KNN) ? sd[lane][ptr] : __int_as_float(0x7f800000);
            int   cj = (ptr < KNN) ? sj[lane][ptr] : 0x7fffffff;
            float wd = cd; int wj = cj;
#pragma unroll
            for (int off = 16; off > 0; off >>= 1) {
                float od = __shfl_xor_sync(0xffffffffu, wd, off);
                int   oj = __shfl_xor_sync(0xffffffffu, wj, off);
                if (od < wd || (od == wd && oj < wj)) { wd = od; wj = oj; }
            }
            if (wd == cd && wj == cj) ptr++;
            if (lane == 0) g_idx[q * KNN + k] = wj;
        }
        __syncwarp();
    }
}

// ---------------------------------------------------------------------------
// Kernel: z[b][n][o] = sum_c W[o][c] * x[b][c][n]   (stored n-major)
// Also zeroes the fallback worklist counter (runs first in stream order).
// ---------------------------------------------------------------------------
__global__ void __launch_bounds__(128) gemm_kernel(const float* __restrict__ x,
                                                   const float* __restrict__ W) {
    if (blockIdx.x == 0 && threadIdx.x == 0) g_wcount = 0;

    __shared__ float ws[COUT * CIN];
    int tid = threadIdx.x;
#pragma unroll
    for (int u = 0; u < 8; u++)
        ((float4*)ws)[tid + u * 128] = ((const float4*)W)[tid + u * 128];
    __syncthreads();

    int b     = blockIdx.x >> 7;          // 128 n-tiles of 64 per batch
    int ntile = (blockIdx.x & 127) * 64;
    int nl    = tid & 63;
    int o0    = (tid >> 6) * 32;
    int n     = ntile + nl;

    const float* xb = x + b * CIN * NPTS;

    float acc[32];
#pragma unroll
    for (int i = 0; i < 32; i++) acc[i] = 0.0f;

    for (int c = 0; c < CIN; c += 4) {
        float xv0 = xb[(c + 0) * NPTS + n];
        float xv1 = xb[(c + 1) * NPTS + n];
        float xv2 = xb[(c + 2) * NPTS + n];
        float xv3 = xb[(c + 3) * NPTS + n];
#pragma unroll
        for (int i = 0; i < 32; i++) {
            float4 w4 = *(const float4*)&ws[(o0 + i) * CIN + c];
            acc[i] = fmaf(w4.x, xv0, acc[i]);
            acc[i] = fmaf(w4.y, xv1, acc[i]);
            acc[i] = fmaf(w4.z, xv2, acc[i]);
            acc[i] = fmaf(w4.w, xv3, acc[i]);
        }
    }

    float* zp = g_z + ((size_t)b * NPTS + n) * COUT + o0;
#pragma unroll
    for (int i = 0; i < 32; i += 4)
        *(float4*)&zp[i] = make_float4(acc[i], acc[i + 1], acc[i + 2], acc[i + 3]);
}

// ---------------------------------------------------------------------------
// Kernel: y[b][o][n] = max_k z[b][idx[b][n][k]][o]; tail blocks copy coords
// into the second output region (replaces the cudaMemcpyAsync node).
// ---------------------------------------------------------------------------
#define MG_BLOCKS   (BB * 256)
#define CP_FLOAT4   (BB * 3 * NPTS / 4)   // 24576 float4 of coords
#define CP_BLOCKS   (CP_FLOAT4 / 256)     // 96

__global__ void __launch_bounds__(256) maxgather_kernel(float* __restrict__ y,
                                                        const float* __restrict__ coords) {
    if (blockIdx.x >= MG_BLOCKS) {
        int i = (blockIdx.x - MG_BLOCKS) * 256 + threadIdx.x;
        float4* dst = (float4*)(y + (size_t)BB * COUT * NPTS);
        dst[i] = ((const float4*)coords)[i];
        return;
    }

    __shared__ float yt[COUT][33];

    int tid = threadIdx.x;
    int w   = tid >> 5;
    int l   = tid & 31;
    int b     = blockIdx.x >> 8;
    int ntile = (blockIdx.x & 255) * 32;

    const float* zb = g_z + (size_t)b * NPTS * COUT;
    const float NEG_INF = __int_as_float(0xff800000);

    for (int qq = 0; qq < 4; qq++) {
        int nl = w * 4 + qq;
        int n  = ntile + nl;
        const int* ip = g_idx + ((size_t)b * NPTS + n) * KNN;
        float m0 = NEG_INF, m1 = NEG_INF;
#pragma unroll
        for (int k = 0; k < KNN; k++) {
            int r = __ldg(&ip[k]);
            const float* zr = zb + (size_t)r * COUT;
            m0 = fmaxf(m0, zr[l]);
            m1 = fmaxf(m1, zr[l + 32]);
        }
        yt[l][nl]      = m0;
        yt[l + 32][nl] = m1;
    }
    __syncthreads();

#pragma unroll
    for (int e = tid; e < COUT * 32; e += 256) {
        int o  = e >> 5;
        int nl = e & 31;
        y[((size_t)b * COUT + o) * NPTS + ntile + nl] = yt[o][nl];
    }
}

// ---------------------------------------------------------------------------
extern "C" void kernel_launch(void* const* d_in, const int* in_sizes, int n_in,
                              void* d_out, int out_size) {
    const float* x      = (const float*)d_in[0];
    const float* coords = (const float*)d_in[1];
    const float* W      = (const float*)d_in[2];
    float*       out    = (float*)d_out;

    gemm_kernel<<<BB * 128, 128>>>(x, W);
    knn_collect<<<NQ / 128, 128>>>(coords);
    knn_fallback<<<256, 32>>>(coords);
    maxgather_kernel<<<MG_BLOCKS + CP_BLOCKS, 256>>>(out, coords);
}